// round 2
// baseline (speedup 1.0000x reference)
#include <cuda_runtime.h>

#define BATCH 16
#define NV    20000
#define FIN   64
#define COUT  64
#define KNB   16
#define TILE_V 64
#define SROW   68   // smem row stride in floats (feature-major rows), 16B aligned

__constant__ float cWx[FIN * COUT];   // [f][c]
__constant__ float cWn[FIN * COUT];   // [f][c]
__constant__ float cBias[COUT];

__global__ __launch_bounds__(256, 6)
void convnet_fused_kernel(const float* __restrict__ x,
                          const int*   __restrict__ neighbor,
                          float*       __restrict__ out)
{
    // Feature-major tiles: row = feature (64 rows), col = vertex (64 + pad)
    __shared__ float sX[FIN * SROW];
    __shared__ float sN[FIN * SROW];

    const int b   = blockIdx.y;
    const int v0  = blockIdx.x * TILE_V;
    const int tid = threadIdx.x;
    const float* __restrict__ xb = x + (size_t)b * NV * FIN;

    // ---------------- Phase 1: load x tile (coalesced), transpose to [f][v]
    #pragma unroll
    for (int it = 0; it < 4; ++it) {
        int linear = tid + it * 256;          // 0..1023 = 64 verts * 16 float4
        int vi = linear >> 4;                 // vertex within tile
        int fq = linear & 15;                 // float4 index along features
        int v  = v0 + vi;
        float4 val = make_float4(0.f, 0.f, 0.f, 0.f);
        if (v < NV)
            val = *(const float4*)(xb + (size_t)v * FIN + fq * 4);
        sX[(fq * 4 + 0) * SROW + vi] = val.x;
        sX[(fq * 4 + 1) * SROW + vi] = val.y;
        sX[(fq * 4 + 2) * SROW + vi] = val.z;
        sX[(fq * 4 + 3) * SROW + vi] = val.w;
    }

    // ---------------- Phase 2: gather + mean (half-warp per vertex) --------
    const int hw  = tid >> 4;   // half-warp id 0..15
    const int l16 = tid & 15;   // lane within half-warp (feature quad)
    #pragma unroll
    for (int vi = hw; vi < TILE_V; vi += 16) {
        const int v = v0 + vi;
        int nid = 0;
        if (v < NV)
            nid = __ldg(&neighbor[v * KNB + l16]);

        float4 acc = make_float4(0.f, 0.f, 0.f, 0.f);
        #pragma unroll
        for (int k = 0; k < KNB; ++k) {
            int r = __shfl_sync(0xffffffffu, nid, k, 16);
            if (r > 0) {   // r==0 is the zero-pad row
                float4 t = *(const float4*)(xb + (size_t)(r - 1) * FIN + l16 * 4);
                acc.x += t.x; acc.y += t.y; acc.z += t.z; acc.w += t.w;
            }
        }
        const float s = 1.0f / (float)KNB;
        sN[(l16 * 4 + 0) * SROW + vi] = acc.x * s;
        sN[(l16 * 4 + 1) * SROW + vi] = acc.y * s;
        sN[(l16 * 4 + 2) * SROW + vi] = acc.z * s;
        sN[(l16 * 4 + 3) * SROW + vi] = acc.w * s;
    }
    __syncthreads();

    // ---------------- Phase 3: dual micro-GEMM, 4 verts x 4 chans / thread -
    // Per f-step: 2x LDS.128 (x,nbm for 4 verts) + 2x LDC.128 (weights) + 32 FFMA
    const int vg = tid & 15;   // vertex group: verts vg*4 .. vg*4+3
    const int cg = tid >> 4;   // channel group: chans cg*4 .. cg*4+3
    float4 acc0, acc1, acc2, acc3;
    {
        const float4 bias = *(const float4*)&cBias[cg * 4];
        acc0 = bias; acc1 = bias; acc2 = bias; acc3 = bias;
    }

    #pragma unroll 2
    for (int f = 0; f < FIN; ++f) {
        const float4 xv = *(const float4*)&sX[f * SROW + vg * 4];
        const float4 nv = *(const float4*)&sN[f * SROW + vg * 4];
        const float4 wx = *(const float4*)&cWx[f * COUT + cg * 4];
        const float4 wn = *(const float4*)&cWn[f * COUT + cg * 4];

        acc0.x += xv.x * wx.x + nv.x * wn.x;  acc0.y += xv.x * wx.y + nv.x * wn.y;
        acc0.z += xv.x * wx.z + nv.x * wn.z;  acc0.w += xv.x * wx.w + nv.x * wn.w;
        acc1.x += xv.y * wx.x + nv.y * wn.x;  acc1.y += xv.y * wx.y + nv.y * wn.y;
        acc1.z += xv.y * wx.z + nv.y * wn.z;  acc1.w += xv.y * wx.w + nv.y * wn.w;
        acc2.x += xv.z * wx.x + nv.z * wn.x;  acc2.y += xv.z * wx.y + nv.z * wn.y;
        acc2.z += xv.z * wx.z + nv.z * wn.z;  acc2.w += xv.z * wx.w + nv.z * wn.w;
        acc3.x += xv.w * wx.x + nv.w * wn.x;  acc3.y += xv.w * wx.y + nv.w * wn.y;
        acc3.z += xv.w * wx.z + nv.w * wn.z;  acc3.w += xv.w * wx.w + nv.w * wn.w;
    }

    // ---------------- Phase 4: store ---------------------------------------
    float* __restrict__ outb = out + (size_t)b * NV * COUT;
    {
        int v = v0 + vg * 4 + 0;
        if (v < NV) *(float4*)(outb + (size_t)v * COUT + cg * 4) = acc0;
        v = v0 + vg * 4 + 1;
        if (v < NV) *(float4*)(outb + (size_t)v * COUT + cg * 4) = acc1;
        v = v0 + vg * 4 + 2;
        if (v < NV) *(float4*)(outb + (size_t)v * COUT + cg * 4) = acc2;
        v = v0 + vg * 4 + 3;
        if (v < NV) *(float4*)(outb + (size_t)v * COUT + cg * 4) = acc3;
    }
}

extern "C" void kernel_launch(void* const* d_in, const int* in_sizes, int n_in,
                              void* d_out, int out_size)
{
    // metadata order: x, Wx, Wn, b, neighbor
    const float* x        = (const float*)d_in[0];
    const void*  Wx       = d_in[1];
    const void*  Wn       = d_in[2];
    const void*  bias     = d_in[3];
    const int*   neighbor = (const int*)d_in[4];
    float*       out      = (float*)d_out;

    cudaMemcpyToSymbolAsync(cWx,   Wx,   FIN * COUT * sizeof(float), 0,
                            cudaMemcpyDeviceToDevice, 0);
    cudaMemcpyToSymbolAsync(cWn,   Wn,   FIN * COUT * sizeof(float), 0,
                            cudaMemcpyDeviceToDevice, 0);
    cudaMemcpyToSymbolAsync(cBias, bias, COUT * sizeof(float), 0,
                            cudaMemcpyDeviceToDevice, 0);

    dim3 grid((NV + TILE_V - 1) / TILE_V, BATCH);
    convnet_fused_kernel<<<grid, 256>>>(x, neighbor, out);
}

// round 3
// speedup vs baseline: 1.1599x; 1.1599x over previous
#include <cuda_runtime.h>

#define BATCH 16
#define NV    20000
#define FIN   64
#define COUT  64
#define KNB   16
#define TILE_V 64
#define SROW   68   // smem row stride (floats) for transposed [f][v] tile

__constant__ float cWx[FIN * COUT];   // [f][c]
__constant__ float cWn[FIN * COUT];   // [f][c]
__constant__ float cBias[COUT];

// Scratch: y = x @ Wn, [B][V][COUT]
__device__ float g_y[(size_t)BATCH * NV * COUT];

// ---------------------------------------------------------------------------
// Kernel A: dense dual GEMM.  out = x@Wx + b  (to d_out),  y = x@Wn (scratch)
// ---------------------------------------------------------------------------
__global__ __launch_bounds__(256)
void gemm_kernel(const float* __restrict__ x,
                 float*       __restrict__ out)
{
    __shared__ float sX[FIN * SROW];   // transposed x tile: [f][v]

    const int b   = blockIdx.y;
    const int v0  = blockIdx.x * TILE_V;
    const int tid = threadIdx.x;
    const float* __restrict__ xb = x + (size_t)b * NV * FIN;

    // Load x tile coalesced, store transposed
    #pragma unroll
    for (int it = 0; it < 4; ++it) {
        int linear = tid + it * 256;          // 64 verts * 16 float4
        int vi = linear >> 4;
        int fq = linear & 15;
        int v  = v0 + vi;
        float4 val = make_float4(0.f, 0.f, 0.f, 0.f);
        if (v < NV)
            val = *(const float4*)(xb + (size_t)v * FIN + fq * 4);
        sX[(fq * 4 + 0) * SROW + vi] = val.x;
        sX[(fq * 4 + 1) * SROW + vi] = val.y;
        sX[(fq * 4 + 2) * SROW + vi] = val.z;
        sX[(fq * 4 + 3) * SROW + vi] = val.w;
    }
    __syncthreads();

    // Dual micro-GEMM: 4 verts x 4 chans per thread, for Wx and Wn
    const int vg = tid & 15;   // verts vg*4 .. vg*4+3
    const int cg = tid >> 4;   // chans cg*4 .. cg*4+3

    float4 ax0, ax1, ax2, ax3;      // x@Wx accumulators (bias-seeded)
    {
        const float4 bias = *(const float4*)&cBias[cg * 4];
        ax0 = bias; ax1 = bias; ax2 = bias; ax3 = bias;
    }
    float4 ay0 = make_float4(0,0,0,0), ay1 = ay0, ay2 = ay0, ay3 = ay0;

    #pragma unroll 8
    for (int f = 0; f < FIN; ++f) {
        const float4 xv = *(const float4*)&sX[f * SROW + vg * 4];
        const float4 wx = *(const float4*)&cWx[f * COUT + cg * 4];
        const float4 wn = *(const float4*)&cWn[f * COUT + cg * 4];

        ax0.x += xv.x * wx.x;  ax0.y += xv.x * wx.y;  ax0.z += xv.x * wx.z;  ax0.w += xv.x * wx.w;
        ax1.x += xv.y * wx.x;  ax1.y += xv.y * wx.y;  ax1.z += xv.y * wx.z;  ax1.w += xv.y * wx.w;
        ax2.x += xv.z * wx.x;  ax2.y += xv.z * wx.y;  ax2.z += xv.z * wx.z;  ax2.w += xv.z * wx.w;
        ax3.x += xv.w * wx.x;  ax3.y += xv.w * wx.y;  ax3.z += xv.w * wx.z;  ax3.w += xv.w * wx.w;

        ay0.x += xv.x * wn.x;  ay0.y += xv.x * wn.y;  ay0.z += xv.x * wn.z;  ay0.w += xv.x * wn.w;
        ay1.x += xv.y * wn.x;  ay1.y += xv.y * wn.y;  ay1.z += xv.y * wn.z;  ay1.w += xv.y * wn.w;
        ay2.x += xv.z * wn.x;  ay2.y += xv.z * wn.y;  ay2.z += xv.z * wn.z;  ay2.w += xv.z * wn.w;
        ay3.x += xv.w * wn.x;  ay3.y += xv.w * wn.y;  ay3.z += xv.w * wn.z;  ay3.w += xv.w * wn.w;
    }

    float* __restrict__ outb = out + (size_t)b * NV * COUT;
    float* __restrict__ yb   = g_y + (size_t)b * NV * COUT;
    #pragma unroll
    for (int r = 0; r < 4; ++r) {
        int v = v0 + vg * 4 + r;
        if (v < NV) {
            float4 a = (r == 0) ? ax0 : (r == 1) ? ax1 : (r == 2) ? ax2 : ax3;
            float4 y = (r == 0) ? ay0 : (r == 1) ? ay1 : (r == 2) ? ay2 : ay3;
            *(float4*)(outb + (size_t)v * COUT + cg * 4) = a;
            *(float4*)(yb   + (size_t)v * COUT + cg * 4) = y;
        }
    }
}

// ---------------------------------------------------------------------------
// Kernel B: out[b,v,:] += (1/K) * sum_k y[b, neighbor[v,k]-1, :]   (0 = pad)
// One warp per (b, v). 16 independent LDG.64 per warp -> MLP=16.
// ---------------------------------------------------------------------------
__global__ __launch_bounds__(256)
void gather_add_kernel(const int* __restrict__ neighbor,
                       float*     __restrict__ out)
{
    const int tid  = threadIdx.x;
    const int warp = tid >> 5;
    const int lane = tid & 31;
    const int v    = blockIdx.x * 8 + warp;     // 2500 * 8 = 20000 exactly
    const int b    = blockIdx.y;

    const float* __restrict__ yb = g_y + (size_t)b * NV * COUT;
    float* __restrict__ op = out + ((size_t)b * NV + v) * COUT + lane * 2;

    // Prefetch existing out row (x@Wx + b part)
    float2 o = *(const float2*)op;

    int nid = 0;
    if (lane < KNB)
        nid = __ldg(&neighbor[v * KNB + lane]);

    float2 acc = make_float2(0.f, 0.f);
    #pragma unroll
    for (int k = 0; k < KNB; ++k) {
        int r = __shfl_sync(0xffffffffu, nid, k);
        if (r > 0) {
            float2 t = *(const float2*)(yb + (size_t)(r - 1) * COUT + lane * 2);
            acc.x += t.x; acc.y += t.y;
        }
    }

    const float s = 1.0f / (float)KNB;
    o.x += acc.x * s;
    o.y += acc.y * s;
    *(float2*)op = o;
}

extern "C" void kernel_launch(void* const* d_in, const int* in_sizes, int n_in,
                              void* d_out, int out_size)
{
    // metadata order: x, Wx, Wn, b, neighbor
    const float* x        = (const float*)d_in[0];
    const void*  Wx       = d_in[1];
    const void*  Wn       = d_in[2];
    const void*  bias     = d_in[3];
    const int*   neighbor = (const int*)d_in[4];
    float*       out      = (float*)d_out;

    cudaMemcpyToSymbolAsync(cWx,   Wx,   FIN * COUT * sizeof(float), 0,
                            cudaMemcpyDeviceToDevice, 0);
    cudaMemcpyToSymbolAsync(cWn,   Wn,   FIN * COUT * sizeof(float), 0,
                            cudaMemcpyDeviceToDevice, 0);
    cudaMemcpyToSymbolAsync(cBias, bias, COUT * sizeof(float), 0,
                            cudaMemcpyDeviceToDevice, 0);

    dim3 gridA((NV + TILE_V - 1) / TILE_V, BATCH);
    gemm_kernel<<<gridA, 256>>>(x, out);

    dim3 gridB(NV / 8, BATCH);   // 2500 x 16
    gather_add_kernel<<<gridB, 256>>>(neighbor, out);
}

// round 4
// speedup vs baseline: 3.8107x; 3.2853x over previous
#include <cuda_runtime.h>
#include <cstdint>

#define BATCH 16
#define NV    20000
#define FIN   64
#define COUT  64
#define KNB   16

// Scratch: y = x @ Wn, [B][V][COUT]
__device__ float g_y[(size_t)BATCH * NV * COUT];
// Weights in mma-fragment order: [mat(2)][ks(8)][nt(8)][lane(32)][2] tf32 bits
__device__ uint32_t g_wfrag[2 * 8 * 8 * 32 * 2];

// ---------------------------------------------------------------------------
// Pre-kernel: swizzle Wx/Wn into m16n8k8 B-fragment order (tf32)
// B frag (col-major 8k x 8n): b0 = W[k = t + 8ks][n = g + 8nt], b1 = W[k+4][n]
// ---------------------------------------------------------------------------
__global__ void wfrag_build_kernel(const float* __restrict__ Wx,
                                   const float* __restrict__ Wn)
{
    int i = blockIdx.x * 256 + threadIdx.x;        // 0..16383
    int j    =  i        & 1;
    int lane = (i >> 1)  & 31;
    int nt   = (i >> 6)  & 7;
    int ks   = (i >> 9)  & 7;
    int mat  =  i >> 12;
    int k = (lane & 3) + 4 * j + 8 * ks;
    int n = (lane >> 2) + 8 * nt;
    const float* W = mat ? Wn : Wx;
    float v = W[k * COUT + n];
    uint32_t tv;
    asm("cvt.rna.tf32.f32 %0, %1;" : "=r"(tv) : "f"(v));
    g_wfrag[i] = tv;
}

// ---------------------------------------------------------------------------
// Kernel A: tensor-core dual GEMM. out = x@Wx + b (d_out), y = x@Wn (scratch)
// CTA = 128 verts x 64 cols, 8 warps; warp = 16 verts x 64 cols, K=64.
// ---------------------------------------------------------------------------
__global__ __launch_bounds__(256)
void gemm_tc_kernel(const float* __restrict__ x,
                    const float* __restrict__ bias,
                    float*       __restrict__ out)
{
    __shared__ uint32_t sW[2 * 8 * 8 * 32 * 2];    // 32 KB

    const int tid = threadIdx.x;

    // Stage fragment-ordered weights: 2048 uint4, 8 per thread, coalesced.
    {
        const uint4* src = (const uint4*)g_wfrag;
        uint4*       dst = (uint4*)sW;
        #pragma unroll
        for (int i = 0; i < 8; ++i)
            dst[tid + i * 256] = src[tid + i * 256];
    }
    __syncthreads();

    const int lane = tid & 31;
    const int wid  = tid >> 5;
    const int g    = lane >> 2;      // group id (row within m-tile)
    const int t    = lane & 3;       // thread-in-group (col phase)
    const int b    = blockIdx.y;
    const int vb   = blockIdx.x * 128 + wid * 16;
    const int r0   = vb + g;
    const int r1   = r0 + 8;

    const float* __restrict__ xb = x + (size_t)b * NV * FIN;

    // ---- Prefetch A: 2 rows x 16 cols (cols == t mod 4). 32 indep LDG.32 --
    float f0[16], f1[16];
    #pragma unroll
    for (int j = 0; j < 16; ++j) {
        int c = t + 4 * j;
        f0[j] = (r0 < NV) ? __ldg(&xb[(size_t)r0 * FIN + c]) : 0.f;
        f1[j] = (r1 < NV) ? __ldg(&xb[(size_t)r1 * FIN + c]) : 0.f;
    }
    uint32_t ar0[16], ar1[16];
    #pragma unroll
    for (int j = 0; j < 16; ++j) {
        asm("cvt.rna.tf32.f32 %0, %1;" : "=r"(ar0[j]) : "f"(f0[j]));
        asm("cvt.rna.tf32.f32 %0, %1;" : "=r"(ar1[j]) : "f"(f1[j]));
    }

    // ---- Mainloop: 8 k-steps x 8 n-tiles x 2 matrices -----------------------
    float accX[8][4] = {{0.f}};
    float accN[8][4] = {{0.f}};

    #pragma unroll
    for (int ks = 0; ks < 8; ++ks) {
        // A frag for this k-step: cols 8ks+t (j=2ks) and 8ks+t+4 (j=2ks+1)
        const uint32_t a0 = ar0[2 * ks];
        const uint32_t a1 = ar1[2 * ks];
        const uint32_t a2 = ar0[2 * ks + 1];
        const uint32_t a3 = ar1[2 * ks + 1];

        #pragma unroll
        for (int nt = 0; nt < 8; ++nt) {
            const uint2 bx = *(const uint2*)&sW[((0 * 8 + ks) * 8 + nt) * 64 + lane * 2];
            const uint2 bn = *(const uint2*)&sW[((1 * 8 + ks) * 8 + nt) * 64 + lane * 2];

            asm volatile(
                "mma.sync.aligned.m16n8k8.row.col.f32.tf32.tf32.f32 "
                "{%0,%1,%2,%3}, {%4,%5,%6,%7}, {%8,%9}, {%0,%1,%2,%3};"
                : "+f"(accX[nt][0]), "+f"(accX[nt][1]),
                  "+f"(accX[nt][2]), "+f"(accX[nt][3])
                : "r"(a0), "r"(a1), "r"(a2), "r"(a3),
                  "r"(bx.x), "r"(bx.y));
            asm volatile(
                "mma.sync.aligned.m16n8k8.row.col.f32.tf32.tf32.f32 "
                "{%0,%1,%2,%3}, {%4,%5,%6,%7}, {%8,%9}, {%0,%1,%2,%3};"
                : "+f"(accN[nt][0]), "+f"(accN[nt][1]),
                  "+f"(accN[nt][2]), "+f"(accN[nt][3])
                : "r"(a0), "r"(a1), "r"(a2), "r"(a3),
                  "r"(bn.x), "r"(bn.y));
        }
    }

    // ---- Epilogue: c0/c1 = row g cols (8nt+2t, +1); c2/c3 = row g+8 --------
    float* __restrict__ outb = out + (size_t)b * NV * COUT;
    float* __restrict__ yb   = g_y + (size_t)b * NV * COUT;
    #pragma unroll
    for (int nt = 0; nt < 8; ++nt) {
        const int c = nt * 8 + 2 * t;
        const float2 bv = *(const float2*)&bias[c];
        if (r0 < NV) {
            *(float2*)&outb[(size_t)r0 * COUT + c] =
                make_float2(accX[nt][0] + bv.x, accX[nt][1] + bv.y);
            *(float2*)&yb[(size_t)r0 * COUT + c] =
                make_float2(accN[nt][0], accN[nt][1]);
        }
        if (r1 < NV) {
            *(float2*)&outb[(size_t)r1 * COUT + c] =
                make_float2(accX[nt][2] + bv.x, accX[nt][3] + bv.y);
            *(float2*)&yb[(size_t)r1 * COUT + c] =
                make_float2(accN[nt][2], accN[nt][3]);
        }
    }
}

// ---------------------------------------------------------------------------
// Kernel B: out[b,v,:] += (1/K) * sum_k y[b, neighbor[v,k]-1, :]   (0 = pad)
// One warp per (b, v). 16 independent row reads -> high MLP, L1/L2 resident.
// ---------------------------------------------------------------------------
__global__ __launch_bounds__(256)
void gather_add_kernel(const int* __restrict__ neighbor,
                       float*     __restrict__ out)
{
    const int tid  = threadIdx.x;
    const int warp = tid >> 5;
    const int lane = tid & 31;
    const int v    = blockIdx.x * 8 + warp;     // 2500 * 8 = 20000 exactly
    const int b    = blockIdx.y;

    const float* __restrict__ yb = g_y + (size_t)b * NV * COUT;
    float* __restrict__ op = out + ((size_t)b * NV + v) * COUT + lane * 2;

    float2 o = *(const float2*)op;

    int nid = 0;
    if (lane < KNB)
        nid = __ldg(&neighbor[v * KNB + lane]);

    float2 acc = make_float2(0.f, 0.f);
    #pragma unroll
    for (int k = 0; k < KNB; ++k) {
        int r = __shfl_sync(0xffffffffu, nid, k);
        if (r > 0) {
            float2 tv = *(const float2*)(yb + (size_t)(r - 1) * COUT + lane * 2);
            acc.x += tv.x; acc.y += tv.y;
        }
    }

    const float s = 1.0f / (float)KNB;
    o.x += acc.x * s;
    o.y += acc.y * s;
    *(float2*)op = o;
}

extern "C" void kernel_launch(void* const* d_in, const int* in_sizes, int n_in,
                              void* d_out, int out_size)
{
    // metadata order: x, Wx, Wn, b, neighbor
    const float* x        = (const float*)d_in[0];
    const float* Wx       = (const float*)d_in[1];
    const float* Wn       = (const float*)d_in[2];
    const float* bias     = (const float*)d_in[3];
    const int*   neighbor = (const int*)d_in[4];
    float*       out      = (float*)d_out;

    wfrag_build_kernel<<<64, 256>>>(Wx, Wn);

    dim3 gridA((NV + 127) / 128, BATCH);        // 157 x 16
    gemm_tc_kernel<<<gridA, 256>>>(x, bias, out);

    dim3 gridB(NV / 8, BATCH);                  // 2500 x 16
    gather_add_kernel<<<gridB, 256>>>(neighbor, out);
}